// round 7
// baseline (speedup 1.0000x reference)
#include <cuda_runtime.h>
#include <cstdint>

#define N_NODES 20000
#define N_EDGES 320000
#define F 128
#define R 4
#define NBUCKETS (R * N_NODES)
#define CAP 64            // max edges per (relation,dst) bucket; Poisson(4) => P(>=64) ~ 1e-60

// ---------------- scratch (device globals; no allocation allowed) ----------------
__device__ float g_A[(size_t)R * N_NODES * F];        // per-relation aggregated messages (41 MB)
__device__ float g_h[(size_t)N_NODES * F];            // layer-1 output
__device__ int   g_cnt[NBUCKETS];                     // bucket fill counts
__device__ int2  g_slots[(size_t)NBUCKETS * CAP];     // (src, w-bits) per bucket slot
__device__ int   g_mn, g_mx;                          // float-as-int min/max (weights >= 0)

// ---------------- init: minmax seeds + zero bucket counters (one launch) ----------------
__global__ void k_init() {
    int i = blockIdx.x * blockDim.x + threadIdx.x;
    if (i == 0) {
        g_mn = 0x7f800000;   // +inf bits
        g_mx = 0;            // 0.0f bits (weights >= 0 so int-compare works)
    }
    if (i < NBUCKETS) g_cnt[i] = 0;
}

__global__ void k_minmax(const float* __restrict__ ew) {
    int i = blockIdx.x * blockDim.x + threadIdx.x;
    float v = (i < N_EDGES) ? ew[i] : ew[0];
    float mn = v, mx = v;
    #pragma unroll
    for (int o = 16; o; o >>= 1) {
        mn = fminf(mn, __shfl_xor_sync(0xffffffffu, mn, o));
        mx = fmaxf(mx, __shfl_xor_sync(0xffffffffu, mx, o));
    }
    if ((threadIdx.x & 31) == 0) {
        atomicMin(&g_mn, __float_as_int(mn));
        atomicMax(&g_mx, __float_as_int(mx));
    }
}

// ---------------- bucket build (once per call, shared by both layers); 2 edges/thread ------
__global__ void k_build(const int* __restrict__ src, const int* __restrict__ dst,
                        const int* __restrict__ et, const float* __restrict__ ew) {
    int base = (blockIdx.x * blockDim.x + threadIdx.x) * 2;
    float mn = __int_as_float(g_mn);
    float mx = __int_as_float(g_mx);
    float inv = 1.0f / (mx - mn + 1e-8f);
    #pragma unroll
    for (int j = 0; j < 2; j++) {
        int e = base + j;
        if (e >= N_EDGES) break;
        float w = (ew[e] - mn) * inv;
        int b = et[e] * N_NODES + dst[e];
        int slot = atomicAdd(&g_cnt[b], 1);
        if (slot < CAP)
            g_slots[(size_t)b * CAP + slot] = make_int2(src[e], __float_as_int(w));
    }
}

// ---------------- aggregate: A[b] = sum over bucket b of w * xin[src]  (no atomics) ----------
// One warp per bucket; chunks of 4 edges with predicated weights -> MLP 4 on row gathers.
__global__ void k_agg(const float* __restrict__ x, int use_h) {
    int b = (int)(((size_t)blockIdx.x * blockDim.x + threadIdx.x) >> 5);
    if (b >= NBUCKETS) return;
    int lane = threadIdx.x & 31;
    const float* xin = use_h ? g_h : x;

    int n = g_cnt[b];
    n = n > CAP ? CAP : n;          // saturate (defensive)
    const int2* sl = g_slots + (size_t)b * CAP;

    float4 acc = make_float4(0.f, 0.f, 0.f, 0.f);
    for (int i = 0; i < n; i += 4) {
        int4 ea = __ldg((const int4*)&sl[i]);
        int4 eb = __ldg((const int4*)&sl[i + 2]);
        float w0 = (i + 0 < n) ? __int_as_float(ea.y) : 0.f;
        float w1 = (i + 1 < n) ? __int_as_float(ea.w) : 0.f;
        float w2 = (i + 2 < n) ? __int_as_float(eb.y) : 0.f;
        float w3 = (i + 3 < n) ? __int_as_float(eb.w) : 0.f;
        unsigned s0 = min((unsigned)ea.x, (unsigned)(N_NODES - 1));
        unsigned s1 = min((unsigned)ea.z, (unsigned)(N_NODES - 1));
        unsigned s2 = min((unsigned)eb.x, (unsigned)(N_NODES - 1));
        unsigned s3 = min((unsigned)eb.z, (unsigned)(N_NODES - 1));
        float4 x0 = ((const float4*)(xin + (size_t)s0 * F))[lane];
        float4 x1 = ((const float4*)(xin + (size_t)s1 * F))[lane];
        float4 x2 = ((const float4*)(xin + (size_t)s2 * F))[lane];
        float4 x3 = ((const float4*)(xin + (size_t)s3 * F))[lane];
        acc.x += w0 * x0.x + w1 * x1.x + w2 * x2.x + w3 * x3.x;
        acc.y += w0 * x0.y + w1 * x1.y + w2 * x2.y + w3 * x3.y;
        acc.z += w0 * x0.z + w1 * x1.z + w2 * x2.z + w3 * x3.z;
        acc.w += w0 * x0.w + w1 * x1.w + w2 * x2.w + w3 * x3.w;
    }
    ((float4*)(g_A + (size_t)b * F))[lane] = acc;
}

// ---------------- tf32 helpers ----------------
__device__ __forceinline__ uint32_t f2tf32(float f) {
    uint32_t r;
    asm("cvt.rna.tf32.f32 %0, %1;" : "=r"(r) : "f"(f));
    return r;
}

#define MMA_TF32(d, a0, a1, a2, a3, b0, b1)                                   \
    asm volatile("mma.sync.aligned.m16n8k8.row.col.f32.tf32.tf32.f32 "        \
                 "{%0,%1,%2,%3}, {%4,%5,%6,%7}, {%8,%9}, {%0,%1,%2,%3};"      \
                 : "+f"((d)[0]), "+f"((d)[1]), "+f"((d)[2]), "+f"((d)[3])     \
                 : "r"(a0), "r"(a1), "r"(a2), "r"(a3), "r"(b0), "r"(b1))

// ---------------- combine: out = relu?( [A0|A1|A2|A3|Xin] @ [W;root] + b ) ----------------
// tf32 tensor-core GEMM, software-pipelined (prefetch next tile into regs during mma).
// BM=64, BN=128, BK=32, 256 threads = 8 warps (2 row-groups x 4 col-groups),
// warp tile 32x32 = 2 m16-tiles x 4 n8-tiles, mma.sync.m16n8k8.
#define NTILES 20   // 5 segments x 4 BK-steps
__global__ void __launch_bounds__(256, 2)
k_combine(const float* __restrict__ Xparam,  // [N,F] (layer-1 input x)
          const float* __restrict__ Wrel,    // [R,F,F]
          const float* __restrict__ root,    // [F,F]
          const float* __restrict__ bias,    // [F]
          float* __restrict__ out_param,     // final out, or nullptr -> g_h
          int do_relu, int use_h) {
    __shared__ uint32_t Xs[64][36];    // tf32 A tile, row-major; pad 36: conflict-free frags
    __shared__ uint32_t Ws[32][136];   // tf32 B tile [k][col];  pad 136: conflict-free frags

    float* out = out_param ? out_param : g_h;
    const float* Xin = use_h ? g_h : Xparam;

    int t    = threadIdx.x;
    int lane = t & 31;
    int w    = t >> 5;          // warp 0..7
    int wm   = w & 1;           // row group: rows wm*32..+31
    int wn   = w >> 1;          // col group: cols wn*32..+31
    int gid  = lane >> 2;       // 0..7
    int tid4 = lane & 3;        // 0..3
    int row0 = blockIdx.x * 64;

    float acc[2][4][4];
    #pragma unroll
    for (int mt = 0; mt < 2; mt++)
        #pragma unroll
        for (int nt = 0; nt < 4; nt++)
            #pragma unroll
            for (int q = 0; q < 4; q++) acc[mt][nt][q] = 0.f;

    // per-thread load coordinates (fixed across tiles)
    // X tile: 64 rows x 32 k = 512 float4 slots, 2 per thread
    int xr[2], xk[2];
    #pragma unroll
    for (int it = 0; it < 2; it++) {
        int idx = t + it * 256;
        xr[it] = idx >> 3;          // 0..63
        xk[it] = (idx & 7) * 4;     // 0..28
    }
    // W tile: 32 k x 128 cols = 1024 float4 slots, 4 per thread
    int wk[4], wc[4];
    #pragma unroll
    for (int it = 0; it < 4; it++) {
        int idx = t + it * 256;
        wk[it] = idx >> 5;          // 0..31
        wc[it] = (idx & 31) * 4;    // 0..124
    }

    float4 px[2], pw[4];
    // tile id -> (segment, k0): seg = tile>>2, k0 = (tile&3)*32
    // segments: 0..3 = g_A relation r with Wrel[r]; 4 = Xin with root
    #define LOAD_TILE(tile)                                                        \
    do {                                                                           \
        int seg_ = (tile) >> 2;                                                    \
        int k0_  = ((tile) & 3) * 32;                                              \
        const float* srcp_ = (seg_ < 4) ? (g_A + (size_t)seg_ * N_NODES * F) : Xin;\
        const float* wseg_ = (seg_ < 4) ? (Wrel + (size_t)seg_ * F * F)      : root;\
        _Pragma("unroll")                                                          \
        for (int it = 0; it < 2; it++) {                                           \
            int grow_ = row0 + xr[it];                                             \
            px[it] = (grow_ < N_NODES)                                             \
                   ? ((const float4*)(srcp_ + (size_t)grow_ * F + k0_ + xk[it]))[0]\
                   : make_float4(0.f, 0.f, 0.f, 0.f);                              \
        }                                                                          \
        _Pragma("unroll")                                                          \
        for (int it = 0; it < 4; it++)                                             \
            pw[it] = ((const float4*)(wseg_ + (size_t)(k0_ + wk[it]) * F + wc[it]))[0];\
    } while (0)

    LOAD_TILE(0);

    for (int tile = 0; tile < NTILES; tile++) {
        __syncthreads();   // previous compute done -> smem reusable
        // store prefetched tile (convert to tf32)
        #pragma unroll
        for (int it = 0; it < 2; it++) {
            uint4 u = make_uint4(f2tf32(px[it].x), f2tf32(px[it].y),
                                 f2tf32(px[it].z), f2tf32(px[it].w));
            *(uint4*)&Xs[xr[it]][xk[it]] = u;
        }
        #pragma unroll
        for (int it = 0; it < 4; it++) {
            uint4 u = make_uint4(f2tf32(pw[it].x), f2tf32(pw[it].y),
                                 f2tf32(pw[it].z), f2tf32(pw[it].w));
            *(uint4*)&Ws[wk[it]][wc[it]] = u;
        }
        __syncthreads();

        // issue next tile's global loads (consumed at next store -> overlapped with mma)
        if (tile + 1 < NTILES) LOAD_TILE(tile + 1);

        #pragma unroll
        for (int kk = 0; kk < 32; kk += 8) {
            uint32_t a[2][4];
            #pragma unroll
            for (int mt = 0; mt < 2; mt++) {
                int row = wm * 32 + mt * 16 + gid;
                a[mt][0] = Xs[row][kk + tid4];
                a[mt][1] = Xs[row + 8][kk + tid4];
                a[mt][2] = Xs[row][kk + tid4 + 4];
                a[mt][3] = Xs[row + 8][kk + tid4 + 4];
            }
            #pragma unroll
            for (int nt = 0; nt < 4; nt++) {
                int col = wn * 32 + nt * 8 + gid;
                uint32_t b0 = Ws[kk + tid4][col];
                uint32_t b1 = Ws[kk + tid4 + 4][col];
                MMA_TF32(acc[0][nt], a[0][0], a[0][1], a[0][2], a[0][3], b0, b1);
                MMA_TF32(acc[1][nt], a[1][0], a[1][1], a[1][2], a[1][3], b0, b1);
            }
        }
    }
    #undef LOAD_TILE

    // epilogue: c-frag rows base+gid / base+gid+8, cols wn*32 + nt*8 + tid4*2 (+1)
    #pragma unroll
    for (int mt = 0; mt < 2; mt++) {
        int rbase = row0 + wm * 32 + mt * 16 + gid;
        #pragma unroll
        for (int half = 0; half < 2; half++) {
            int grow = rbase + half * 8;
            if (grow >= N_NODES) continue;
            #pragma unroll
            for (int nt = 0; nt < 4; nt++) {
                int col = wn * 32 + nt * 8 + tid4 * 2;
                float v0 = acc[mt][nt][half * 2 + 0] + __ldg(&bias[col]);
                float v1 = acc[mt][nt][half * 2 + 1] + __ldg(&bias[col + 1]);
                if (do_relu) { v0 = fmaxf(v0, 0.f); v1 = fmaxf(v1, 0.f); }
                *(float2*)(out + (size_t)grow * F + col) = make_float2(v0, v1);
            }
        }
    }
}

// ---------------- launcher ----------------
extern "C" void kernel_launch(void* const* d_in, const int* in_sizes, int n_in,
                              void* d_out, int out_size) {
    const float* x     = (const float*)d_in[0];
    const int*   ei    = (const int*)d_in[1];     // [2, E]
    const int*   srcp  = ei;
    const int*   dstp  = ei + N_EDGES;
    const int*   et    = (const int*)d_in[2];
    const float* ew    = (const float*)d_in[3];
    const float* W1    = (const float*)d_in[4];
    const float* root1 = (const float*)d_in[5];
    const float* b1    = (const float*)d_in[6];
    const float* W2    = (const float*)d_in[7];
    const float* root2 = (const float*)d_in[8];
    const float* b2    = (const float*)d_in[9];
    float* out = (float*)d_out;

    const int eblocks  = (N_EDGES + 255) / 256;
    const int bblocks  = (N_EDGES / 2 + 255) / 256;
    const int cblocks  = (N_NODES + 63) / 64;
    const int ablocks  = (NBUCKETS * 32 + 255) / 256;   // one warp per bucket
    const int iblocks  = (NBUCKETS + 255) / 256;

    // init (minmax seeds + counter zeroing), minmax, bucket build (shared by both layers)
    k_init<<<iblocks, 256>>>();
    k_minmax<<<eblocks, 256>>>(ew);
    k_build<<<bblocks, 256>>>(srcp, dstp, et, ew);

    // layer 1: A = gather-aggregate(x); h = relu([A|x] @ [W1;root1] + b1)
    k_agg<<<ablocks, 256>>>(x, /*use_h=*/0);
    k_combine<<<cblocks, 256>>>(x, W1, root1, b1, /*out=*/nullptr, /*relu=*/1, /*use_h=*/0);

    // layer 2: A = gather-aggregate(h); out = [A|h] @ [W2;root2] + b2
    k_agg<<<ablocks, 256>>>(x, /*use_h=*/1);
    k_combine<<<cblocks, 256>>>(x, W2, root2, b2, out, /*relu=*/0, /*use_h=*/1);
}

// round 9
// speedup vs baseline: 1.1564x; 1.1564x over previous
#include <cuda_runtime.h>
#include <cuda_fp16.h>
#include <cstdint>

#define N_NODES 20000
#define N_EDGES 320000
#define F 128
#define R 4
#define NBUCKETS (R * N_NODES)
#define CAP 64            // max edges per (relation,dst) bucket; Poisson(4) => P(>=64) ~ 1e-60
#define NTILES 20         // 5 K-segments x 4 k-chunks of 32

// ---------------- scratch (device globals; no allocation allowed) ----------------
__device__ float    g_A[(size_t)R * N_NODES * F];     // per-relation aggregated messages
__device__ float    g_h[(size_t)N_NODES * F];         // layer-1 output
__device__ int      g_cnt[NBUCKETS];
__device__ int2     g_slots[(size_t)NBUCKETS * CAP];
__device__ int      g_mn, g_mx;
__device__ uint32_t g_Wth[2 * 5 * 4 * 128 * 16];      // [layer][seg][kc][n][k-pair] half2

// ---------------- init: minmax seeds + zero bucket counters ----------------
__global__ void k_init() {
    int i = blockIdx.x * blockDim.x + threadIdx.x;
    if (i == 0) { g_mn = 0x7f800000; g_mx = 0; }
    if (i < NBUCKETS) g_cnt[i] = 0;
}

__global__ void k_minmax(const float* __restrict__ ew) {
    int i = blockIdx.x * blockDim.x + threadIdx.x;
    float v = (i < N_EDGES) ? ew[i] : ew[0];
    float mn = v, mx = v;
    #pragma unroll
    for (int o = 16; o; o >>= 1) {
        mn = fminf(mn, __shfl_xor_sync(0xffffffffu, mn, o));
        mx = fmaxf(mx, __shfl_xor_sync(0xffffffffu, mx, o));
    }
    if ((threadIdx.x & 31) == 0) {
        atomicMin(&g_mn, __float_as_int(mn));
        atomicMax(&g_mx, __float_as_int(mx));
    }
}

// ---------------- pack two fp32 -> half2 bits (lo = first arg) ----------------
__device__ __forceinline__ uint32_t pack_h2(float a, float b) {
    __half2 h = __floats2half2_rn(a, b);
    return *(uint32_t*)&h;
}

// ---------------- W transpose + fp16 preconvert: g_Wth[layer][seg][kc][n][kpair] ---
// Source W layout: [k][n] row-major per segment. Pack pairs (k=2j, k=2j+1) per col n.
__global__ void k_wt(const float* __restrict__ W1, const float* __restrict__ r1,
                     const float* __restrict__ W2, const float* __restrict__ r2) {
    int idx = blockIdx.x * blockDim.x + threadIdx.x;   // 2*5*128*64 = 81920 half2 slots
    if (idx >= 2 * 5 * 128 * 64) return;
    int layer = idx / 40960;
    int rem   = idx % 40960;
    int seg   = rem / 8192;
    int nj    = rem % 8192;        // n*64 + j
    int n     = nj >> 6;
    int j     = nj & 63;           // k-pair 0..63
    const float* src = (layer == 0) ? ((seg < 4) ? W1 + seg * 16384 : r1)
                                    : ((seg < 4) ? W2 + seg * 16384 : r2);
    uint32_t v = pack_h2(src[(2 * j) * 128 + n], src[(2 * j + 1) * 128 + n]);
    g_Wth[((((size_t)layer * 5 + seg) * 4 + (j >> 4)) * 128 + n) * 16 + (j & 15)] = v;
}

// ---------------- bucket build; 2 edges/thread ----------------
__global__ void k_build(const int* __restrict__ src, const int* __restrict__ dst,
                        const int* __restrict__ et, const float* __restrict__ ew) {
    int base = (blockIdx.x * blockDim.x + threadIdx.x) * 2;
    float mn = __int_as_float(g_mn);
    float mx = __int_as_float(g_mx);
    float inv = 1.0f / (mx - mn + 1e-8f);
    #pragma unroll
    for (int j = 0; j < 2; j++) {
        int e = base + j;
        if (e >= N_EDGES) break;
        float w = (ew[e] - mn) * inv;
        int b = et[e] * N_NODES + dst[e];
        int slot = atomicAdd(&g_cnt[b], 1);
        if (slot < CAP)
            g_slots[(size_t)b * CAP + slot] = make_int2(src[e], __float_as_int(w));
    }
}

// ---------------- aggregate (unchanged; measured 24.7us) ----------------
__global__ void k_agg(const float* __restrict__ x, int use_h) {
    int b = (int)(((size_t)blockIdx.x * blockDim.x + threadIdx.x) >> 5);
    if (b >= NBUCKETS) return;
    int lane = threadIdx.x & 31;
    const float* xin = use_h ? g_h : x;

    int n = g_cnt[b];
    n = n > CAP ? CAP : n;
    const int2* sl = g_slots + (size_t)b * CAP;

    float4 acc = make_float4(0.f, 0.f, 0.f, 0.f);
    for (int i = 0; i < n; i += 4) {
        int4 ea = __ldg((const int4*)&sl[i]);
        int4 eb = __ldg((const int4*)&sl[i + 2]);
        float w0 = (i + 0 < n) ? __int_as_float(ea.y) : 0.f;
        float w1 = (i + 1 < n) ? __int_as_float(ea.w) : 0.f;
        float w2 = (i + 2 < n) ? __int_as_float(eb.y) : 0.f;
        float w3 = (i + 3 < n) ? __int_as_float(eb.w) : 0.f;
        unsigned s0 = min((unsigned)ea.x, (unsigned)(N_NODES - 1));
        unsigned s1 = min((unsigned)ea.z, (unsigned)(N_NODES - 1));
        unsigned s2 = min((unsigned)eb.x, (unsigned)(N_NODES - 1));
        unsigned s3 = min((unsigned)eb.z, (unsigned)(N_NODES - 1));
        float4 x0 = ((const float4*)(xin + (size_t)s0 * F))[lane];
        float4 x1 = ((const float4*)(xin + (size_t)s1 * F))[lane];
        float4 x2 = ((const float4*)(xin + (size_t)s2 * F))[lane];
        float4 x3 = ((const float4*)(xin + (size_t)s3 * F))[lane];
        acc.x += w0 * x0.x + w1 * x1.x + w2 * x2.x + w3 * x3.x;
        acc.y += w0 * x0.y + w1 * x1.y + w2 * x2.y + w3 * x3.y;
        acc.z += w0 * x0.z + w1 * x1.z + w2 * x2.z + w3 * x3.z;
        acc.w += w0 * x0.w + w1 * x1.w + w2 * x2.w + w3 * x3.w;
    }
    ((float4*)(g_A + (size_t)b * F))[lane] = acc;
}

#define MMA_F16(d, a0, a1, a2, a3, b0, b1)                                    \
    asm volatile("mma.sync.aligned.m16n8k16.row.col.f32.f16.f16.f32 "         \
                 "{%0,%1,%2,%3}, {%4,%5,%6,%7}, {%8,%9}, {%0,%1,%2,%3};"      \
                 : "+f"((d)[0]), "+f"((d)[1]), "+f"((d)[2]), "+f"((d)[3])     \
                 : "r"(a0), "r"(a1), "r"(a2), "r"(a3), "r"(b0), "r"(b1))

// ---------------- combine: out = relu?( [A0|A1|A2|A3|Xin] @ [W;root] + b ) ----------------
// fp16 tensor-core GEMM (m16n8k16, fp32 accumulate; fp16 mantissa == tf32 mantissa).
// BM=64, BN=128, BK=32, 256 threads = 8 warps (2 row-groups x 4 col-groups),
// warp tile 32x32 = 2 m16-tiles x 4 n8-tiles. Prefetch-to-regs pipeline.
// Smem stride 20 uint32 -> all fragment LDS conflict-free (cosets {0,20,8,28,...}+tid4).
__global__ void __launch_bounds__(256, 2)
k_combine(const float* __restrict__ Xparam,  // [N,F] (layer-1 input x)
          const float* __restrict__ bias,    // [F]
          float* __restrict__ out_param,     // final out, or nullptr -> g_h
          int do_relu, int use_h, int layer) {
    __shared__ uint32_t Xs[64][20];    // half2 A tile: 16 k-pairs + pad 4
    __shared__ uint32_t Wh[128][20];   // half2 B tile [col][k-pair]: 16 + pad 4

    float* out = out_param ? out_param : g_h;
    const float* Xin = use_h ? g_h : Xparam;

    int t    = threadIdx.x;
    int lane = t & 31;
    int w    = t >> 5;          // warp 0..7
    int wm   = w & 1;           // row group: rows wm*32..+31
    int wn   = w >> 1;          // col group: cols wn*32..+31
    int gid  = lane >> 2;       // 0..7
    int tid4 = lane & 3;        // 0..3
    int row0 = blockIdx.x * 64;

    float acc[2][4][4];
    #pragma unroll
    for (int mt = 0; mt < 2; mt++)
        #pragma unroll
        for (int nt = 0; nt < 4; nt++)
            #pragma unroll
            for (int q = 0; q < 4; q++) acc[mt][nt][q] = 0.f;

    // per-thread load coordinates (fixed across tiles)
    // A tile: 64 rows x 8 float4 (32 floats) = 512 slots, 2/thread
    int xr[2], xj[2];
    #pragma unroll
    for (int it = 0; it < 2; it++) {
        int idx = t + it * 256;
        xr[it] = idx >> 3;          // 0..63
        xj[it] = idx & 7;           // float4 slot -> half2 pair base 2*xj
    }
    // B tile: 128 cols x 4 uint4 (16 half2) = 512 slots, 2/thread
    int wn_[2], wq[2];
    #pragma unroll
    for (int it = 0; it < 2; it++) {
        int idx = t + it * 256;
        wn_[it] = idx >> 2;         // 0..127
        wq[it]  = idx & 3;          // uint4 slot -> half2 base 4*wq
    }

    float4 px[2]; uint4 pw[2];
    #define LOAD_TILE(tile)                                                         \
    do {                                                                            \
        int seg_ = (tile) >> 2;                                                     \
        int kc_  = (tile) & 3;                                                      \
        int k0_  = kc_ * 32;                                                        \
        const float* srcp_ = (seg_ < 4) ? (g_A + (size_t)seg_ * N_NODES * F) : Xin; \
        const uint32_t* wt_ = g_Wth + (((size_t)layer * 5 + seg_) * 4 + kc_) * 2048;\
        _Pragma("unroll")                                                           \
        for (int it = 0; it < 2; it++) {                                            \
            int grow_ = row0 + xr[it];                                              \
            px[it] = (grow_ < N_NODES)                                              \
                   ? ((const float4*)(srcp_ + (size_t)grow_ * F + k0_ + xj[it] * 4))[0] \
                   : make_float4(0.f, 0.f, 0.f, 0.f);                               \
            pw[it] = *(const uint4*)(wt_ + wn_[it] * 16 + wq[it] * 4);              \
        }                                                                           \
    } while (0)

    LOAD_TILE(0);

    for (int tile = 0; tile < NTILES; tile++) {
        __syncthreads();   // previous compute done -> smem reusable
        // store prefetched tile (A converted fp32->half2; B pre-packed)
        #pragma unroll
        for (int it = 0; it < 2; it++) {
            uint2 u = make_uint2(pack_h2(px[it].x, px[it].y), pack_h2(px[it].z, px[it].w));
            *(uint2*)&Xs[xr[it]][xj[it] * 2] = u;
            *(uint4*)&Wh[wn_[it]][wq[it] * 4] = pw[it];
        }
        __syncthreads();

        // issue next tile's global loads (overlap with mma)
        if (tile + 1 < NTILES) LOAD_TILE(tile + 1);

        // 2 x K=16 steps (half2 offsets 0, 8)
        #pragma unroll
        for (int kk = 0; kk < 16; kk += 8) {
            uint32_t a[2][4];
            #pragma unroll
            for (int mt = 0; mt < 2; mt++) {
                int row = wm * 32 + mt * 16 + gid;
                a[mt][0] = Xs[row][kk + tid4];
                a[mt][1] = Xs[row + 8][kk + tid4];
                a[mt][2] = Xs[row][kk + tid4 + 4];
                a[mt][3] = Xs[row + 8][kk + tid4 + 4];
            }
            #pragma unroll
            for (int nt = 0; nt < 4; nt++) {
                int col = wn * 32 + nt * 8 + gid;
                uint32_t b0 = Wh[col][kk + tid4];
                uint32_t b1 = Wh[col][kk + tid4 + 4];
                MMA_F16(acc[0][nt], a[0][0], a[0][1], a[0][2], a[0][3], b0, b1);
                MMA_F16(acc[1][nt], a[1][0], a[1][1], a[1][2], a[1][3], b0, b1);
            }
        }
    }
    #undef LOAD_TILE

    // epilogue: c-frag rows base+gid / base+gid+8, cols wn*32 + nt*8 + tid4*2 (+1)
    #pragma unroll
    for (int mt = 0; mt < 2; mt++) {
        int rbase = row0 + wm * 32 + mt * 16 + gid;
        #pragma unroll
        for (int half = 0; half < 2; half++) {
            int grow = rbase + half * 8;
            if (grow >= N_NODES) continue;
            #pragma unroll
            for (int nt = 0; nt < 4; nt++) {
                int col = wn * 32 + nt * 8 + tid4 * 2;
                float v0 = acc[mt][nt][half * 2 + 0] + __ldg(&bias[col]);
                float v1 = acc[mt][nt][half * 2 + 1] + __ldg(&bias[col + 1]);
                if (do_relu) { v0 = fmaxf(v0, 0.f); v1 = fmaxf(v1, 0.f); }
                *(float2*)(out + (size_t)grow * F + col) = make_float2(v0, v1);
            }
        }
    }
}

// ---------------- launcher ----------------
extern "C" void kernel_launch(void* const* d_in, const int* in_sizes, int n_in,
                              void* d_out, int out_size) {
    const float* x     = (const float*)d_in[0];
    const int*   ei    = (const int*)d_in[1];     // [2, E]
    const int*   srcp  = ei;
    const int*   dstp  = ei + N_EDGES;
    const int*   et    = (const int*)d_in[2];
    const float* ew    = (const float*)d_in[3];
    const float* W1    = (const float*)d_in[4];
    const float* root1 = (const float*)d_in[5];
    const float* b1    = (const float*)d_in[6];
    const float* W2    = (const float*)d_in[7];
    const float* root2 = (const float*)d_in[8];
    const float* b2    = (const float*)d_in[9];
    float* out = (float*)d_out;

    const int eblocks  = (N_EDGES + 255) / 256;
    const int bblocks  = (N_EDGES / 2 + 255) / 256;
    const int cblocks  = (N_NODES + 63) / 64;                 // 313
    const int ablocks  = (NBUCKETS * 32 + 255) / 256;
    const int iblocks  = (NBUCKETS + 255) / 256;
    const int wtblocks = (2 * 5 * 128 * 64 + 255) / 256;

    // prep: init, W transpose/fp16-pack, minmax, bucket build
    k_init<<<iblocks, 256>>>();
    k_wt<<<wtblocks, 256>>>(W1, root1, W2, root2);
    k_minmax<<<eblocks, 256>>>(ew);
    k_build<<<bblocks, 256>>>(srcp, dstp, et, ew);

    // layer 1: A = gather-aggregate(x); h = relu([A|x] @ [W1;root1] + b1)
    k_agg<<<ablocks, 256>>>(x, /*use_h=*/0);
    k_combine<<<cblocks, 256>>>(x, b1, /*out=*/nullptr, /*relu=*/1, /*use_h=*/0, /*layer=*/0);

    // layer 2: A = gather-aggregate(h); out = [A|h] @ [W2;root2] + b2
    k_agg<<<ablocks, 256>>>(x, /*use_h=*/1);
    k_combine<<<cblocks, 256>>>(x, b2, out, /*relu=*/0, /*use_h=*/1, /*layer=*/1);
}

// round 10
// speedup vs baseline: 1.2667x; 1.0954x over previous
#include <cuda_runtime.h>
#include <cuda_fp16.h>
#include <cstdint>

#define N_NODES 20000
#define N_EDGES 320000
#define F 128
#define FH 64             // F/2 half2 per row
#define R 4
#define NBUCKETS (R * N_NODES)
#define CAP 64            // max edges per (relation,dst) bucket; Poisson(4) => P(>=64) ~ 1e-60
#define NTILES 20         // 5 K-segments x 4 k-chunks of 32

// ---------------- scratch (device globals; no allocation allowed) ----------------
__device__ uint32_t g_Ah[(size_t)R * N_NODES * FH];   // per-relation messages, half2 (20.5 MB)
__device__ uint32_t g_xh[(size_t)N_NODES * FH];       // x in half2 (5 MB)
__device__ uint32_t g_hh[(size_t)N_NODES * FH];       // layer-1 output in half2 (5 MB)
__device__ int      g_cnt[NBUCKETS];
__device__ int2     g_slots[(size_t)NBUCKETS * CAP];
__device__ int      g_mn, g_mx;
__device__ uint32_t g_Wth[2 * 5 * 4 * 128 * 16];      // [layer][seg][kc][n][k-pair] half2

__device__ __forceinline__ uint32_t pack_h2(float a, float b) {
    __half2 h = __floats2half2_rn(a, b);
    return *(uint32_t*)&h;
}
__device__ __forceinline__ float2 unpack_h2(uint32_t u) {
    return __half22float2(*(__half2*)&u);
}

// ---------------- init: minmax seeds + zero bucket counters ----------------
__global__ void k_init() {
    int i = blockIdx.x * blockDim.x + threadIdx.x;
    if (i == 0) { g_mn = 0x7f800000; g_mx = 0; }
    if (i < NBUCKETS) g_cnt[i] = 0;
}

__global__ void k_minmax(const float* __restrict__ ew) {
    int i = blockIdx.x * blockDim.x + threadIdx.x;
    float v = (i < N_EDGES) ? ew[i] : ew[0];
    float mn = v, mx = v;
    #pragma unroll
    for (int o = 16; o; o >>= 1) {
        mn = fminf(mn, __shfl_xor_sync(0xffffffffu, mn, o));
        mx = fmaxf(mx, __shfl_xor_sync(0xffffffffu, mx, o));
    }
    if ((threadIdx.x & 31) == 0) {
        atomicMin(&g_mn, __float_as_int(mn));
        atomicMax(&g_mx, __float_as_int(mx));
    }
}

// ---------------- x -> half2 preconvert ----------------
__global__ void k_xh(const float* __restrict__ x) {
    int i = blockIdx.x * blockDim.x + threadIdx.x;   // half2 index
    if (i >= N_NODES * FH) return;
    float2 v = ((const float2*)x)[i];
    g_xh[i] = pack_h2(v.x, v.y);
}

// ---------------- W transpose + fp16 preconvert: g_Wth[layer][seg][kc][n][kpair] ---
__global__ void k_wt(const float* __restrict__ W1, const float* __restrict__ r1,
                     const float* __restrict__ W2, const float* __restrict__ r2) {
    int idx = blockIdx.x * blockDim.x + threadIdx.x;   // 2*5*128*64 half2 slots
    if (idx >= 2 * 5 * 128 * 64) return;
    int layer = idx / 40960;
    int rem   = idx % 40960;
    int seg   = rem / 8192;
    int nj    = rem % 8192;        // n*64 + j
    int n     = nj >> 6;
    int j     = nj & 63;           // k-pair 0..63
    const float* src = (layer == 0) ? ((seg < 4) ? W1 + seg * 16384 : r1)
                                    : ((seg < 4) ? W2 + seg * 16384 : r2);
    uint32_t v = pack_h2(src[(2 * j) * 128 + n], src[(2 * j + 1) * 128 + n]);
    g_Wth[((((size_t)layer * 5 + seg) * 4 + (j >> 4)) * 128 + n) * 16 + (j & 15)] = v;
}

// ---------------- bucket build; 2 edges/thread ----------------
__global__ void k_build(const int* __restrict__ src, const int* __restrict__ dst,
                        const int* __restrict__ et, const float* __restrict__ ew) {
    int base = (blockIdx.x * blockDim.x + threadIdx.x) * 2;
    float mn = __int_as_float(g_mn);
    float mx = __int_as_float(g_mx);
    float inv = 1.0f / (mx - mn + 1e-8f);
    #pragma unroll
    for (int j = 0; j < 2; j++) {
        int e = base + j;
        if (e >= N_EDGES) break;
        float w = (ew[e] - mn) * inv;
        int b = et[e] * N_NODES + dst[e];
        int slot = atomicAdd(&g_cnt[b], 1);
        if (slot < CAP)
            g_slots[(size_t)b * CAP + slot] = make_int2(src[e], __float_as_int(w));
    }
}

// ---------------- aggregate: Ah[b] = sum over bucket of w * xin[src] (half2 gather) -------
// One warp per bucket; each lane owns 2 half2 (4 floats); fp32 accumulate, half2 store.
__global__ void k_agg(int use_h) {
    int b = (int)(((size_t)blockIdx.x * blockDim.x + threadIdx.x) >> 5);
    if (b >= NBUCKETS) return;
    int lane = threadIdx.x & 31;
    const uint32_t* xin = use_h ? g_hh : g_xh;

    int n = g_cnt[b];
    n = n > CAP ? CAP : n;
    const int2* sl = g_slots + (size_t)b * CAP;

    float a0 = 0.f, a1 = 0.f, a2 = 0.f, a3 = 0.f;
    for (int i = 0; i < n; i += 4) {
        int4 ea = __ldg((const int4*)&sl[i]);
        int4 eb = __ldg((const int4*)&sl[i + 2]);
        float w0 = (i + 0 < n) ? __int_as_float(ea.y) : 0.f;
        float w1 = (i + 1 < n) ? __int_as_float(ea.w) : 0.f;
        float w2 = (i + 2 < n) ? __int_as_float(eb.y) : 0.f;
        float w3 = (i + 3 < n) ? __int_as_float(eb.w) : 0.f;
        unsigned s0 = min((unsigned)ea.x, (unsigned)(N_NODES - 1));
        unsigned s1 = min((unsigned)ea.z, (unsigned)(N_NODES - 1));
        unsigned s2 = min((unsigned)eb.x, (unsigned)(N_NODES - 1));
        unsigned s3 = min((unsigned)eb.z, (unsigned)(N_NODES - 1));
        // 4 independent 256B row gathers (uint2 per lane = 2 half2)
        uint2 p0 = *(const uint2*)(xin + (size_t)s0 * FH + lane * 2);
        uint2 p1 = *(const uint2*)(xin + (size_t)s1 * FH + lane * 2);
        uint2 p2 = *(const uint2*)(xin + (size_t)s2 * FH + lane * 2);
        uint2 p3 = *(const uint2*)(xin + (size_t)s3 * FH + lane * 2);
        float2 v;
        v = unpack_h2(p0.x); a0 += w0 * v.x; a1 += w0 * v.y;
        v = unpack_h2(p0.y); a2 += w0 * v.x; a3 += w0 * v.y;
        v = unpack_h2(p1.x); a0 += w1 * v.x; a1 += w1 * v.y;
        v = unpack_h2(p1.y); a2 += w1 * v.x; a3 += w1 * v.y;
        v = unpack_h2(p2.x); a0 += w2 * v.x; a1 += w2 * v.y;
        v = unpack_h2(p2.y); a2 += w2 * v.x; a3 += w2 * v.y;
        v = unpack_h2(p3.x); a0 += w3 * v.x; a1 += w3 * v.y;
        v = unpack_h2(p3.y); a2 += w3 * v.x; a3 += w3 * v.y;
    }
    uint2 o = make_uint2(pack_h2(a0, a1), pack_h2(a2, a3));
    *(uint2*)(g_Ah + (size_t)b * FH + lane * 2) = o;
}

#define MMA_F16(d, a0, a1, a2, a3, b0, b1)                                    \
    asm volatile("mma.sync.aligned.m16n8k16.row.col.f32.f16.f16.f32 "         \
                 "{%0,%1,%2,%3}, {%4,%5,%6,%7}, {%8,%9}, {%0,%1,%2,%3};"      \
                 : "+f"((d)[0]), "+f"((d)[1]), "+f"((d)[2]), "+f"((d)[3])     \
                 : "r"(a0), "r"(a1), "r"(a2), "r"(a3), "r"(b0), "r"(b1))

// ---------------- combine: out = relu?( [A0|A1|A2|A3|Xin] @ [W;root] + b ) ----------------
// fp16 tensor-core GEMM (m16n8k16, fp32 acc). All inputs pre-packed half2: STS is pure copy.
// BM=64, BN=128, BK=32, 256 threads = 8 warps (2x4), warp tile 32x32.
// layer==0: Xin=g_xh, relu, half2 store to g_hh. layer==1: Xin=g_hh, fp32 store to out.
__global__ void __launch_bounds__(256, 2)
k_combine(const float* __restrict__ bias, float* __restrict__ out, int layer) {
    __shared__ uint32_t Xs[64][20];    // half2 A tile: 16 k-pairs + pad 4
    __shared__ uint32_t Wh[128][20];   // half2 B tile [col][k-pair]: 16 + pad 4

    const uint32_t* Xin = (layer == 0) ? g_xh : g_hh;

    int t    = threadIdx.x;
    int lane = t & 31;
    int w    = t >> 5;          // warp 0..7
    int wm   = w & 1;           // row group: rows wm*32..+31
    int wn   = w >> 1;          // col group: cols wn*32..+31
    int gid  = lane >> 2;       // 0..7
    int tid4 = lane & 3;        // 0..3
    int row0 = blockIdx.x * 64;

    float acc[2][4][4];
    #pragma unroll
    for (int mt = 0; mt < 2; mt++)
        #pragma unroll
        for (int nt = 0; nt < 4; nt++)
            #pragma unroll
            for (int q = 0; q < 4; q++) acc[mt][nt][q] = 0.f;

    // per-thread load coordinates (fixed across tiles)
    int arow = t >> 2;          // A: 64 rows x 4 uint4 slots; 1 slot/thread
    int aq   = t & 3;           // uint4 slot -> half2 base aq*4
    int wn_[2], wq[2];          // B: 128 cols x 4 uint4 slots; 2 slots/thread
    #pragma unroll
    for (int it = 0; it < 2; it++) {
        int idx = t + it * 256;
        wn_[it] = idx >> 2;
        wq[it]  = idx & 3;
    }

    uint4 pa, pw[2];
    #define LOAD_TILE(tile)                                                         \
    do {                                                                            \
        int seg_ = (tile) >> 2;                                                     \
        int kc_  = (tile) & 3;                                                      \
        const uint32_t* srcA_ = (seg_ < 4) ? (g_Ah + (size_t)seg_ * N_NODES * FH) : Xin; \
        const uint32_t* wt_ = g_Wth + (((size_t)layer * 5 + seg_) * 4 + kc_) * 2048;\
        int grow_ = row0 + arow;                                                    \
        pa = (grow_ < N_NODES)                                                      \
           ? *(const uint4*)(srcA_ + (size_t)grow_ * FH + kc_ * 16 + aq * 4)        \
           : make_uint4(0u, 0u, 0u, 0u);                                            \
        _Pragma("unroll")                                                           \
        for (int it = 0; it < 2; it++)                                              \
            pw[it] = *(const uint4*)(wt_ + wn_[it] * 16 + wq[it] * 4);              \
    } while (0)

    LOAD_TILE(0);

    for (int tile = 0; tile < NTILES; tile++) {
        __syncthreads();   // previous compute done -> smem reusable
        *(uint4*)&Xs[arow][aq * 4] = pa;
        #pragma unroll
        for (int it = 0; it < 2; it++)
            *(uint4*)&Wh[wn_[it]][wq[it] * 4] = pw[it];
        __syncthreads();

        if (tile + 1 < NTILES) LOAD_TILE(tile + 1);

        #pragma unroll
        for (int kk = 0; kk < 16; kk += 8) {
            uint32_t a[2][4];
            #pragma unroll
            for (int mt = 0; mt < 2; mt++) {
                int row = wm * 32 + mt * 16 + gid;
                a[mt][0] = Xs[row][kk + tid4];
                a[mt][1] = Xs[row + 8][kk + tid4];
                a[mt][2] = Xs[row][kk + tid4 + 4];
                a[mt][3] = Xs[row + 8][kk + tid4 + 4];
            }
            #pragma unroll
            for (int nt = 0; nt < 4; nt++) {
                int col = wn * 32 + nt * 8 + gid;
                uint32_t b0 = Wh[col][kk + tid4];
                uint32_t b1 = Wh[col][kk + tid4 + 4];
                MMA_F16(acc[0][nt], a[0][0], a[0][1], a[0][2], a[0][3], b0, b1);
                MMA_F16(acc[1][nt], a[1][0], a[1][1], a[1][2], a[1][3], b0, b1);
            }
        }
    }
    #undef LOAD_TILE

    // epilogue: c-frag rows base+gid / base+gid+8, cols wn*32 + nt*8 + tid4*2 (+1)
    #pragma unroll
    for (int mt = 0; mt < 2; mt++) {
        int rbase = row0 + wm * 32 + mt * 16 + gid;
        #pragma unroll
        for (int half = 0; half < 2; half++) {
            int grow = rbase + half * 8;
            if (grow >= N_NODES) continue;
            #pragma unroll
            for (int nt = 0; nt < 4; nt++) {
                int col = wn * 32 + nt * 8 + tid4 * 2;
                float v0 = acc[mt][nt][half * 2 + 0] + __ldg(&bias[col]);
                float v1 = acc[mt][nt][half * 2 + 1] + __ldg(&bias[col + 1]);
                if (layer == 0) {
                    v0 = fmaxf(v0, 0.f); v1 = fmaxf(v1, 0.f);
                    g_hh[(size_t)grow * FH + (col >> 1)] = pack_h2(v0, v1);
                } else {
                    *(float2*)(out + (size_t)grow * F + col) = make_float2(v0, v1);
                }
            }
        }
    }
}

// ---------------- launcher ----------------
extern "C" void kernel_launch(void* const* d_in, const int* in_sizes, int n_in,
                              void* d_out, int out_size) {
    const float* x     = (const float*)d_in[0];
    const int*   ei    = (const int*)d_in[1];     // [2, E]
    const int*   srcp  = ei;
    const int*   dstp  = ei + N_EDGES;
    const int*   et    = (const int*)d_in[2];
    const float* ew    = (const float*)d_in[3];
    const float* W1    = (const float*)d_in[4];
    const float* root1 = (const float*)d_in[5];
    const float* b1    = (const float*)d_in[6];
    const float* W2    = (const float*)d_in[7];
    const float* root2 = (const float*)d_in[8];
    const float* b2    = (const float*)d_in[9];
    float* out = (float*)d_out;

    const int eblocks  = (N_EDGES + 255) / 256;
    const int bblocks  = (N_EDGES / 2 + 255) / 256;
    const int cblocks  = (N_NODES + 63) / 64;                 // 313
    const int ablocks  = (NBUCKETS * 32 + 255) / 256;
    const int iblocks  = (NBUCKETS + 255) / 256;
    const int wtblocks = (2 * 5 * 128 * 64 + 255) / 256;
    const int xblocks  = (N_NODES * FH + 255) / 256;

    // prep: init, x->fp16, W transpose/fp16-pack, minmax, bucket build
    k_init<<<iblocks, 256>>>();
    k_xh<<<xblocks, 256>>>(x);
    k_wt<<<wtblocks, 256>>>(W1, root1, W2, root2);
    k_minmax<<<eblocks, 256>>>(ew);
    k_build<<<bblocks, 256>>>(srcp, dstp, et, ew);

    // layer 1: Ah = gather(g_xh); g_hh = relu([Ah|xh] @ [W1;root1] + b1)
    k_agg<<<ablocks, 256>>>(/*use_h=*/0);
    k_combine<<<cblocks, 256>>>(b1, out, /*layer=*/0);

    // layer 2: Ah = gather(g_hh); out = [Ah|hh] @ [W2;root2] + b2
    k_agg<<<ablocks, 256>>>(/*use_h=*/1);
    k_combine<<<cblocks, 256>>>(b2, out, /*layer=*/1);
}

// round 12
// speedup vs baseline: 1.3409x; 1.0586x over previous
#include <cuda_runtime.h>
#include <cuda_fp16.h>
#include <cstdint>

#define N_NODES 20000
#define N_EDGES 320000
#define F 128
#define FH 64             // F/2 half2 per row
#define R 4
#define NBUCKETS (R * N_NODES)
#define CAP 64            // max edges per (relation,dst) bucket; Poisson(4) => P(>=64) ~ 1e-60
#define NTILES 20         // 5 K-segments x 4 k-chunks of 32

// fused-prep block ranges
#define PREP_I 313        // zero counters + seed minmax
#define PREP_X 5000       // x -> half2
#define PREP_W 320        // W pack
#define PREP_TOTAL (PREP_I + PREP_X + PREP_W)

// ---------------- scratch (device globals; no allocation allowed) ----------------
__device__ uint32_t g_Ah[(size_t)R * N_NODES * FH];   // per-relation messages, half2 (20.5 MB)
__device__ uint32_t g_xh[(size_t)N_NODES * FH];       // x in half2 (5 MB)
__device__ uint32_t g_hh[(size_t)N_NODES * FH];       // layer-1 output in half2 (5 MB)
__device__ int      g_cnt[NBUCKETS];
__device__ int2     g_slots[(size_t)NBUCKETS * CAP];
__device__ int      g_mn, g_mx;
__device__ uint32_t g_Wth[2 * 5 * 4 * 128 * 16];      // [layer][seg][kc][n][k-pair] half2

__device__ __forceinline__ uint32_t pack_h2(float a, float b) {
    __half2 h = __floats2half2_rn(a, b);
    return *(uint32_t*)&h;
}
__device__ __forceinline__ float2 unpack_h2(uint32_t u) {
    return __half22float2(*(__half2*)&u);
}

// ---------------- fused prep: counters+seeds | x->fp16 | W pack (one launch) -------------
__global__ void k_prep(const float* __restrict__ x,
                       const float* __restrict__ W1, const float* __restrict__ r1,
                       const float* __restrict__ W2, const float* __restrict__ r2) {
    int blk = blockIdx.x;
    if (blk < PREP_I) {
        int i = blk * 256 + threadIdx.x;
        if (i == 0) { g_mn = 0x7f800000; g_mx = 0; }
        if (i < NBUCKETS) g_cnt[i] = 0;
    } else if (blk < PREP_I + PREP_X) {
        int i = (blk - PREP_I) * 256 + threadIdx.x;   // half2 index
        if (i < N_NODES * FH) {
            float2 v = ((const float2*)x)[i];
            g_xh[i] = pack_h2(v.x, v.y);
        }
    } else {
        int idx = (blk - PREP_I - PREP_X) * 256 + threadIdx.x;  // 2*5*128*64 half2 slots
        if (idx < 2 * 5 * 128 * 64) {
            int layer = idx / 40960;
            int rem   = idx % 40960;
            int seg   = rem / 8192;
            int nj    = rem % 8192;        // n*64 + j
            int n     = nj >> 6;
            int j     = nj & 63;           // k-pair 0..63
            const float* src = (layer == 0) ? ((seg < 4) ? W1 + seg * 16384 : r1)
                                            : ((seg < 4) ? W2 + seg * 16384 : r2);
            uint32_t v = pack_h2(src[(2 * j) * 128 + n], src[(2 * j + 1) * 128 + n]);
            g_Wth[((((size_t)layer * 5 + seg) * 4 + (j >> 4)) * 128 + n) * 16 + (j & 15)] = v;
        }
    }
}

// ---------------- minmax: grid-stride + block reduction -> 2 atomics/block ----------------
__global__ void k_minmax(const float* __restrict__ ew) {
    __shared__ float smn[8], smx[8];
    int tid  = threadIdx.x;
    int lane = tid & 31;
    int wid  = tid >> 5;

    float mn = __int_as_float(0x7f800000), mx = 0.f;
    for (int i = blockIdx.x * blockDim.x + tid; i < N_EDGES; i += gridDim.x * blockDim.x) {
        float v = ew[i];
        mn = fminf(mn, v);
        mx = fmaxf(mx, v);
    }
    #pragma unroll
    for (int o = 16; o; o >>= 1) {
        mn = fminf(mn, __shfl_xor_sync(0xffffffffu, mn, o));
        mx = fmaxf(mx, __shfl_xor_sync(0xffffffffu, mx, o));
    }
    if (lane == 0) { smn[wid] = mn; smx[wid] = mx; }
    __syncthreads();
    if (wid == 0) {
        mn = smn[lane & 7]; mx = smx[lane & 7];
        #pragma unroll
        for (int o = 4; o; o >>= 1) {
            mn = fminf(mn, __shfl_xor_sync(0xffffffffu, mn, o));
            mx = fmaxf(mx, __shfl_xor_sync(0xffffffffu, mx, o));
        }
        if (lane == 0) {
            atomicMin(&g_mn, __float_as_int(mn));
            atomicMax(&g_mx, __float_as_int(mx));
        }
    }
}

// ---------------- bucket build; 2 edges/thread ----------------
__global__ void k_build(const int* __restrict__ src, const int* __restrict__ dst,
                        const int* __restrict__ et, const float* __restrict__ ew) {
    int base = (blockIdx.x * blockDim.x + threadIdx.x) * 2;
    float mn = __int_as_float(g_mn);
    float mx = __int_as_float(g_mx);
    float inv = 1.0f / (mx - mn + 1e-8f);
    #pragma unroll
    for (int j = 0; j < 2; j++) {
        int e = base + j;
        if (e >= N_EDGES) break;
        float w = (ew[e] - mn) * inv;
        int b = et[e] * N_NODES + dst[e];
        int slot = atomicAdd(&g_cnt[b], 1);
        if (slot < CAP)
            g_slots[(size_t)b * CAP + slot] = make_int2(src[e], __float_as_int(w));
    }
}

// ---------------- aggregate: Ah[b] = sum over bucket of w * xin[src] (half2 gather) -------
__global__ void k_agg(int use_h) {
    int b = (int)(((size_t)blockIdx.x * blockDim.x + threadIdx.x) >> 5);
    if (b >= NBUCKETS) return;
    int lane = threadIdx.x & 31;
    const uint32_t* xin = use_h ? g_hh : g_xh;

    int n = g_cnt[b];
    n = n > CAP ? CAP : n;
    const int2* sl = g_slots + (size_t)b * CAP;

    float a0 = 0.f, a1 = 0.f, a2 = 0.f, a3 = 0.f;
    for (int i = 0; i < n; i += 4) {
        int4 ea = __ldg((const int4*)&sl[i]);
        int4 eb = __ldg((const int4*)&sl[i + 2]);
        float w0 = (i + 0 < n) ? __int_as_float(ea.y) : 0.f;
        float w1 = (i + 1 < n) ? __int_as_float(ea.w) : 0.f;
        float w2 = (i + 2 < n) ? __int_as_float(eb.y) : 0.f;
        float w3 = (i + 3 < n) ? __int_as_float(eb.w) : 0.f;
        unsigned s0 = min((unsigned)ea.x, (unsigned)(N_NODES - 1));
        unsigned s1 = min((unsigned)ea.z, (unsigned)(N_NODES - 1));
        unsigned s2 = min((unsigned)eb.x, (unsigned)(N_NODES - 1));
        unsigned s3 = min((unsigned)eb.z, (unsigned)(N_NODES - 1));
        uint2 p0 = *(const uint2*)(xin + (size_t)s0 * FH + lane * 2);
        uint2 p1 = *(const uint2*)(xin + (size_t)s1 * FH + lane * 2);
        uint2 p2 = *(const uint2*)(xin + (size_t)s2 * FH + lane * 2);
        uint2 p3 = *(const uint2*)(xin + (size_t)s3 * FH + lane * 2);
        float2 v;
        v = unpack_h2(p0.x); a0 += w0 * v.x; a1 += w0 * v.y;
        v = unpack_h2(p0.y); a2 += w0 * v.x; a3 += w0 * v.y;
        v = unpack_h2(p1.x); a0 += w1 * v.x; a1 += w1 * v.y;
        v = unpack_h2(p1.y); a2 += w1 * v.x; a3 += w1 * v.y;
        v = unpack_h2(p2.x); a0 += w2 * v.x; a1 += w2 * v.y;
        v = unpack_h2(p2.y); a2 += w2 * v.x; a3 += w2 * v.y;
        v = unpack_h2(p3.x); a0 += w3 * v.x; a1 += w3 * v.y;
        v = unpack_h2(p3.y); a2 += w3 * v.x; a3 += w3 * v.y;
    }
    uint2 o = make_uint2(pack_h2(a0, a1), pack_h2(a2, a3));
    *(uint2*)(g_Ah + (size_t)b * FH + lane * 2) = o;
}

#define MMA_F16(d, a0, a1, a2, a3, b0, b1)                                    \
    asm volatile("mma.sync.aligned.m16n8k16.row.col.f32.f16.f16.f32 "         \
                 "{%0,%1,%2,%3}, {%4,%5,%6,%7}, {%8,%9}, {%0,%1,%2,%3};"      \
                 : "+f"((d)[0]), "+f"((d)[1]), "+f"((d)[2]), "+f"((d)[3])     \
                 : "r"(a0), "r"(a1), "r"(a2), "r"(a3), "r"(b0), "r"(b1))

// ---------------- combine: out = relu?( [A0|A1|A2|A3|Xin] @ [W;root] + b ) ----------------
// fp16 tensor-core GEMM (m16n8k16, fp32 acc). All inputs pre-packed half2: STS is pure copy.
// BM=64, BN=128, BK=32, 256 threads = 8 warps (2x4), warp tile 32x32.
__global__ void __launch_bounds__(256, 2)
k_combine(const float* __restrict__ bias, float* __restrict__ out, int layer) {
    __shared__ uint32_t Xs[64][20];    // half2 A tile: 16 k-pairs + pad 4
    __shared__ uint32_t Wh[128][20];   // half2 B tile [col][k-pair]: 16 + pad 4

    const uint32_t* Xin = (layer == 0) ? g_xh : g_hh;

    int t    = threadIdx.x;
    int lane = t & 31;
    int w    = t >> 5;          // warp 0..7
    int wm   = w & 1;           // row group: rows wm*32..+31
    int wn   = w >> 1;          // col group: cols wn*32..+31
    int gid  = lane >> 2;       // 0..7
    int tid4 = lane & 3;        // 0..3
    int row0 = blockIdx.x * 64;

    float acc[2][4][4];
    #pragma unroll
    for (int mt = 0; mt < 2; mt++)
        #pragma unroll
        for (int nt = 0; nt < 4; nt++)
            #pragma unroll
            for (int q = 0; q < 4; q++) acc[mt][nt][q] = 0.f;

    int arow = t >> 2;          // A: 64 rows x 4 uint4 slots; 1/thread
    int aq   = t & 3;
    int wn_[2], wq[2];          // B: 128 cols x 4 uint4 slots; 2/thread
    #pragma unroll
    for (int it = 0; it < 2; it++) {
        int idx = t + it * 256;
        wn_[it] = idx >> 2;
        wq[it]  = idx & 3;
    }

    uint4 pa, pw[2];
    #define LOAD_TILE(tile)                                                         \
    do {                                                                            \
        int seg_ = (tile) >> 2;                                                     \
        int kc_  = (tile) & 3;                                                      \
        const uint32_t* srcA_ = (seg_ < 4) ? (g_Ah + (size_t)seg_ * N_NODES * FH) : Xin; \
        const uint32_t* wt_ = g_Wth + (((size_t)layer * 5 + seg_) * 4 + kc_) * 2048;\
        int grow_ = row0 + arow;                                                    \
        pa = (grow_ < N_NODES)                                                      \
           ? *(const uint4*)(srcA_ + (size_t)grow_ * FH + kc_ * 16 + aq * 4)        \
           : make_uint4(0u, 0u, 0u, 0u);                                            \
        _Pragma("unroll")                                                           \
        for (int it = 0; it < 2; it++)                                              \
            pw[it] = *(const uint4*)(wt_ + wn_[it] * 16 + wq[it] * 4);              \
    } while (0)

    LOAD_TILE(0);

    for (int tile = 0; tile < NTILES; tile++) {
        __syncthreads();
        *(uint4*)&Xs[arow][aq * 4] = pa;
        #pragma unroll
        for (int it = 0; it < 2; it++)
            *(uint4*)&Wh[wn_[it]][wq[it] * 4] = pw[it];
        __syncthreads();

        if (tile + 1 < NTILES) LOAD_TILE(tile + 1);

        #pragma unroll
        for (int kk = 0; kk < 16; kk += 8) {
            uint32_t a[2][4];
            #pragma unroll
            for (int mt = 0; mt < 2; mt++) {
                int row = wm * 32 + mt * 16 + gid;
                a[mt][0] = Xs[row][kk + tid4];
                a[mt][1] = Xs[row + 8][kk + tid4];
                a[mt][2] = Xs[row][kk + tid4 + 4];
                a[mt][3] = Xs[row + 8][kk + tid4 + 4];
            }
            #pragma unroll
            for (int nt = 0; nt < 4; nt++) {
                int col = wn * 32 + nt * 8 + gid;
                uint32_t b0 = Wh[col][kk + tid4];
                uint32_t b1 = Wh[col][kk + tid4 + 4];
                MMA_F16(acc[0][nt], a[0][0], a[0][1], a[0][2], a[0][3], b0, b1);
                MMA_F16(acc[1][nt], a[1][0], a[1][1], a[1][2], a[1][3], b0, b1);
            }
        }
    }
    #undef LOAD_TILE

    #pragma unroll
    for (int mt = 0; mt < 2; mt++) {
        int rbase = row0 + wm * 32 + mt * 16 + gid;
        #pragma unroll
        for (int half = 0; half < 2; half++) {
            int grow = rbase + half * 8;
            if (grow >= N_NODES) continue;
            #pragma unroll
            for (int nt = 0; nt < 4; nt++) {
                int col = wn * 32 + nt * 8 + tid4 * 2;
                float v0 = acc[mt][nt][half * 2 + 0] + __ldg(&bias[col]);
                float v1 = acc[mt][nt][half * 2 + 1] + __ldg(&bias[col + 1]);
                if (layer == 0) {
                    v0 = fmaxf(v0, 0.f); v1 = fmaxf(v1, 0.f);
                    g_hh[(size_t)grow * FH + (col >> 1)] = pack_h2(v0, v1);
                } else {
                    *(float2*)(out + (size_t)grow * F + col) = make_float2(v0, v1);
                }
            }
        }
    }
}

// ---------------- launcher ----------------
extern "C" void kernel_launch(void* const* d_in, const int* in_sizes, int n_in,
                              void* d_out, int out_size) {
    const float* x     = (const float*)d_in[0];
    const int*   ei    = (const int*)d_in[1];     // [2, E]
    const int*   srcp  = ei;
    const int*   dstp  = ei + N_EDGES;
    const int*   et    = (const int*)d_in[2];
    const float* ew    = (const float*)d_in[3];
    const float* W1    = (const float*)d_in[4];
    const float* root1 = (const float*)d_in[5];
    const float* b1    = (const float*)d_in[6];
    const float* W2    = (const float*)d_in[7];
    const float* root2 = (const float*)d_in[8];
    const float* b2    = (const float*)d_in[9];
    float* out = (float*)d_out;

    const int bblocks  = (N_EDGES / 2 + 255) / 256;
    const int cblocks  = (N_NODES + 63) / 64;                 // 313
    const int ablocks  = (NBUCKETS * 32 + 255) / 256;

    // prep: fused init/x->fp16/W-pack, then minmax (block-reduced), then bucket build
    k_prep<<<PREP_TOTAL, 256>>>(x, W1, root1, W2, root2);
    k_minmax<<<296, 256>>>(ew);
    k_build<<<bblocks, 256>>>(srcp, dstp, et, ew);

    // layer 1: Ah = gather(g_xh); g_hh = relu([Ah|xh] @ [W1;root1] + b1)
    k_agg<<<ablocks, 256>>>(/*use_h=*/0);
    k_combine<<<cblocks, 256>>>(b1, out, /*layer=*/0);

    // layer 2: Ah = gather(g_hh); out = [Ah|hh] @ [W2;root2] + b2
    k_agg<<<ablocks, 256>>>(/*use_h=*/1);
    k_combine<<<cblocks, 256>>>(b2, out, /*layer=*/1);
}